// round 3
// baseline (speedup 1.0000x reference)
#include <cuda_runtime.h>

// IFOPooling: h_t = f_t * h_{t-1} + i_t * z_t over seq (innermost, S=2048),
// B*H = 16384 independent rows. HBM-bound: 512MB total traffic.
//
// R3: two rows per warp. Per tile (512 elems per row):
//   - 24 coalesced LDG.128 issued up front (both rows' f/z/i)  -> 2x MLP
//   - 4 sub-tile affine scans per row, the two rows' shuffle chains
//     interleaved so serial shfl latency (~26cyc/step) is overlapped.
// Lane l owns float4 index (tile*128 + sub*32 + l): dense 512B warp
// requests, 100% sector utilization (kept from R2). Streaming hints.

#define SEQ 2048

__global__ void __launch_bounds__(256) ifo_scan_kernel(
    const float4* __restrict__ f4,
    const float4* __restrict__ z4,
    const float4* __restrict__ i4,
    float4* __restrict__ o4,
    int nwarps)
{
    const int gwarp = (blockIdx.x * blockDim.x + threadIdx.x) >> 5;
    const int lane  = threadIdx.x & 31;
    if (gwarp >= nwarps) return;

    const int rowA4 = (gwarp * 2)     * (SEQ / 4);
    const int rowB4 = (gwarp * 2 + 1) * (SEQ / 4);

    float ha = 0.0f, hb = 0.0f;   // carries for the two rows

    #pragma unroll
    for (int t = 0; t < 4; ++t) {
        const int offA = rowA4 + t * 128 + lane;
        const int offB = rowB4 + t * 128 + lane;

        // ---- load both rows' tiles up front (24 coalesced LDG.128) ----
        float4 fa[4], xa[4], fb[4], xb[4];
        #pragma unroll
        for (int j = 0; j < 4; ++j) {
            float4 ff = __ldcs(&f4[offA + j * 32]);
            float4 zz = __ldcs(&z4[offA + j * 32]);
            float4 ii = __ldcs(&i4[offA + j * 32]);
            fa[j] = ff;
            xa[j] = make_float4(ii.x * zz.x, ii.y * zz.y, ii.z * zz.z, ii.w * zz.w);
        }
        #pragma unroll
        for (int j = 0; j < 4; ++j) {
            float4 ff = __ldcs(&f4[offB + j * 32]);
            float4 zz = __ldcs(&z4[offB + j * 32]);
            float4 ii = __ldcs(&i4[offB + j * 32]);
            fb[j] = ff;
            xb[j] = make_float4(ii.x * zz.x, ii.y * zz.y, ii.z * zz.z, ii.w * zz.w);
        }

        // ---- 4 sub-tile scans, the two rows interleaved ----
        #pragma unroll
        for (int j = 0; j < 4; ++j) {
            // local affine maps (independent chains A and B)
            float Aa, ba, Ab, bb;
            ba = xa[j].x;                    Aa = fa[j].x;
            bb = xb[j].x;                    Ab = fb[j].x;
            ba = fmaf(fa[j].y, ba, xa[j].y); Aa *= fa[j].y;
            bb = fmaf(fb[j].y, bb, xb[j].y); Ab *= fb[j].y;
            ba = fmaf(fa[j].z, ba, xa[j].z); Aa *= fa[j].z;
            bb = fmaf(fb[j].z, bb, xb[j].z); Ab *= fb[j].z;
            ba = fmaf(fa[j].w, ba, xa[j].w); Aa *= fa[j].w;
            bb = fmaf(fb[j].w, bb, xb[j].w); Ab *= fb[j].w;

            // interleaved warp scans: 4 shfls per step, two indep dep-chains
            #pragma unroll
            for (int d = 1; d < 32; d <<= 1) {
                float Apa = __shfl_up_sync(0xffffffffu, Aa, d);
                float bpa = __shfl_up_sync(0xffffffffu, ba, d);
                float Apb = __shfl_up_sync(0xffffffffu, Ab, d);
                float bpb = __shfl_up_sync(0xffffffffu, bb, d);
                if (lane >= d) {
                    ba = fmaf(Aa, bpa, ba);  Aa *= Apa;
                    bb = fmaf(Ab, bpb, bb);  Ab *= Apb;
                }
            }

            // incoming carry per lane (exclusive prefix applied to carry)
            float Aexa = __shfl_up_sync(0xffffffffu, Aa, 1);
            float bexa = __shfl_up_sync(0xffffffffu, ba, 1);
            float Aexb = __shfl_up_sync(0xffffffffu, Ab, 1);
            float bexb = __shfl_up_sync(0xffffffffu, bb, 1);
            float hina = (lane == 0) ? ha : fmaf(Aexa, ha, bexa);
            float hinb = (lane == 0) ? hb : fmaf(Aexb, hb, bexb);

            // sub-tile carry-out from lane 31
            float A31a = __shfl_sync(0xffffffffu, Aa, 31);
            float b31a = __shfl_sync(0xffffffffu, ba, 31);
            float A31b = __shfl_sync(0xffffffffu, Ab, 31);
            float b31b = __shfl_sync(0xffffffffu, bb, 31);

            // emit (two coalesced STG.128)
            float4 ova, ovb;
            float u = hina, v = hinb;
            u = fmaf(fa[j].x, u, xa[j].x); ova.x = u;
            v = fmaf(fb[j].x, v, xb[j].x); ovb.x = v;
            u = fmaf(fa[j].y, u, xa[j].y); ova.y = u;
            v = fmaf(fb[j].y, v, xb[j].y); ovb.y = v;
            u = fmaf(fa[j].z, u, xa[j].z); ova.z = u;
            v = fmaf(fb[j].z, v, xb[j].z); ovb.z = v;
            u = fmaf(fa[j].w, u, xa[j].w); ova.w = u;
            v = fmaf(fb[j].w, v, xb[j].w); ovb.w = v;
            __stcs(&o4[offA + j * 32], ova);
            __stcs(&o4[offB + j * 32], ovb);

            ha = fmaf(A31a, ha, b31a);
            hb = fmaf(A31b, hb, b31b);
        }
    }
}

extern "C" void kernel_launch(void* const* d_in, const int* in_sizes, int n_in,
                              void* d_out, int out_size)
{
    const float4* f = (const float4*)d_in[0];
    const float4* z = (const float4*)d_in[1];
    const float4* i = (const float4*)d_in[2];
    float4* o = (float4*)d_out;

    const int rows = in_sizes[0] / SEQ;      // B*H = 16384
    const int nwarps = rows / 2;             // two rows per warp
    const int block = 256;
    const int grid = (nwarps * 32 + block - 1) / block;

    ifo_scan_kernel<<<grid, block>>>(f, z, i, o, nwarps);
}